// round 2
// baseline (speedup 1.0000x reference)
#include <cuda_runtime.h>
#include <math.h>

#define B_ 64
#define T_ 200
#define L_ 100
#define S_ 8
#define XC_ 16
#define H_ 256
#define W_ 128
#define O_ 8

// ---------------- smem layout (floats) ----------------
// sW0   32768   (mlp_w0 128x256)
// sW1   16384   (mlp_w1 128x128)
// sB2    4096   (mlp_b2)
// sb0     128
// sb1     128
// sbn     256   (gru_bn)
// sz      256   (h / z state)
// szt     256   (vf input argument)
// sa0     128
// sa1     128
// sk     1536   (k1..k6, aliased as GRU gate scratch)
// sdx      16
// sx       32
// smisc    32
// total 56144 floats = 224576 bytes
#define SMEM_FLOATS 56144

__device__ __forceinline__ float warp_red(float v) {
    v += __shfl_xor_sync(0xffffffffu, v, 16);
    v += __shfl_xor_sync(0xffffffffu, v, 8);
    v += __shfl_xor_sync(0xffffffffu, v, 4);
    v += __shfl_xor_sync(0xffffffffu, v, 2);
    v += __shfl_xor_sync(0xffffffffu, v, 1);
    return v;
}

__device__ __forceinline__ float softplus_(float x) {
    float e = __expf(-fabsf(x));
    return fmaxf(x, 0.0f) + __logf(1.0f + e);
}

__device__ __forceinline__ float sigmoid_(float x) {
    return 1.0f / (1.0f + __expf(-x));
}

// vf(z, dxdt):
//   a0 = softplus(W0 @ z + b0)          (128 x 256)  W0 in SMEM
//   a1 = softplus(W1 @ a0 + b1)         (128 x 128)  W1 in SMEM
//   f  = tanh(W2 @ a1 + b2)  (4096x128) W2 streamed from L2
//   out[h] = sum_c f[h*16+c] * dxdt[c]
__device__ void vf_eval(const float* __restrict__ sW0,
                        const float* __restrict__ sW1,
                        const float* __restrict__ sB2,
                        const float* __restrict__ sb0,
                        const float* __restrict__ sb1,
                        const float* __restrict__ zin,
                        const float* __restrict__ sdx,
                        const float4* __restrict__ W2v,
                        float* __restrict__ sa0,
                        float* __restrict__ sa1,
                        float* __restrict__ kout,
                        int wid, int lane) {
    // ---- stage 1: a0 ----
    for (int row = wid; row < W_; row += 8) {
        const float* wr = sW0 + row * H_;
        float v = 0.0f;
#pragma unroll
        for (int k = 0; k < 8; k++) v = fmaf(wr[k * 32 + lane], zin[k * 32 + lane], v);
        v = warp_red(v);
        if (lane == 0) sa0[row] = softplus_(v + sb0[row]);
    }
    __syncthreads();
    // ---- stage 2: a1 ----
    for (int row = wid; row < W_; row += 8) {
        const float* wr = sW1 + row * W_;
        float v = 0.0f;
#pragma unroll
        for (int k = 0; k < 4; k++) v = fmaf(wr[k * 32 + lane], sa0[k * 32 + lane], v);
        v = warp_red(v);
        if (lane == 0) sa1[row] = softplus_(v + sb1[row]);
    }
    __syncthreads();
    // ---- stage 3: big W2 matvec + tanh + contraction with dxdt ----
    // warp w owns h in [w*32, w*32+32). lane split: 4 groups of 8 lanes.
    // group g handles column c = it*4+g of the (h, c) row; each of the 8 lanes
    // loads a contiguous float4 slot so every LDG.128 covers a full 128B chunk.
    const int g = lane >> 3;
    const int l8 = lane & 7;
    float4 ra[4];
    const float4* a1v = (const float4*)sa1;
#pragma unroll
    for (int j = 0; j < 4; j++) ra[j] = a1v[j * 8 + l8];
    float dxg[4];
#pragma unroll
    for (int it = 0; it < 4; it++) dxg[it] = sdx[it * 4 + g];

    const int hbase = wid * 32;
    for (int h = hbase; h < hbase + 32; h++) {
        float acc = 0.0f;
#pragma unroll
        for (int it = 0; it < 4; it++) {
            int row = (h << 4) + (it << 2) + g;
            const float4* wp = W2v + row * 32 + l8;
            float4 w0 = __ldg(wp);
            float4 w1 = __ldg(wp + 8);
            float4 w2 = __ldg(wp + 16);
            float4 w3 = __ldg(wp + 24);
            float s = w0.x * ra[0].x;
            s = fmaf(w0.y, ra[0].y, s);
            s = fmaf(w0.z, ra[0].z, s);
            s = fmaf(w0.w, ra[0].w, s);
            s = fmaf(w1.x, ra[1].x, s);
            s = fmaf(w1.y, ra[1].y, s);
            s = fmaf(w1.z, ra[1].z, s);
            s = fmaf(w1.w, ra[1].w, s);
            s = fmaf(w2.x, ra[2].x, s);
            s = fmaf(w2.y, ra[2].y, s);
            s = fmaf(w2.z, ra[2].z, s);
            s = fmaf(w2.w, ra[2].w, s);
            s = fmaf(w3.x, ra[3].x, s);
            s = fmaf(w3.y, ra[3].y, s);
            s = fmaf(w3.z, ra[3].z, s);
            s = fmaf(w3.w, ra[3].w, s);
            // reduce across the 8 lanes of this group
            s += __shfl_xor_sync(0xffffffffu, s, 1);
            s += __shfl_xor_sync(0xffffffffu, s, 2);
            s += __shfl_xor_sync(0xffffffffu, s, 4);
            float tv = tanhf(s + sB2[row]);
            acc = fmaf(tv, dxg[it], acc);
        }
        // combine the 4 groups (each holds its partial over 4 c's)
        acc += __shfl_xor_sync(0xffffffffu, acc, 8);
        acc += __shfl_xor_sync(0xffffffffu, acc, 16);
        if (lane == 0) kout[h] = acc;
    }
    __syncthreads();
}

extern "C" __global__ void __launch_bounds__(256, 1)
grucde_kernel(const float* __restrict__ y_past, const float* __restrict__ t,
              const float* __restrict__ cx, const float* __restrict__ wih,
              const float* __restrict__ whh, const float* __restrict__ gb,
              const float* __restrict__ gbn, const float* __restrict__ w0,
              const float* __restrict__ b0, const float* __restrict__ w1,
              const float* __restrict__ b1, const float* __restrict__ w2,
              const float* __restrict__ b2, const float* __restrict__ row_,
              const float* __restrict__ rob, float* __restrict__ out) {
    extern __shared__ float sm[];
    float* sW0 = sm;              // 32768
    float* sW1 = sW0 + 32768;     // 16384
    float* sB2 = sW1 + 16384;     // 4096
    float* sb0 = sB2 + 4096;      // 128
    float* sb1 = sb0 + 128;       // 128
    float* sbn = sb1 + 128;       // 256
    float* sz = sbn + 256;        // 256
    float* szt = sz + 256;        // 256
    float* sa0 = szt + 256;       // 128
    float* sa1 = sa0 + 128;       // 128
    float* sk = sa1 + 128;        // 1536
    float* sdx = sk + 1536;       // 16
    float* sx = sdx + 16;         // 32
    float* smisc = sx + 32;       // 32

    const int tid = threadIdx.x;
    const int wid = tid >> 5;
    const int lane = tid & 31;
    const int b = blockIdx.x;
    const float4* W2v = (const float4*)w2;

    // ---- stage weights into SMEM ----
    {
        float4* d = (float4*)sW0;
        const float4* s4 = (const float4*)w0;
        for (int i = tid; i < 8192; i += 256) d[i] = s4[i];
        d = (float4*)sW1;
        s4 = (const float4*)w1;
        for (int i = tid; i < 4096; i += 256) d[i] = s4[i];
        d = (float4*)sB2;
        s4 = (const float4*)b2;
        for (int i = tid; i < 1024; i += 256) d[i] = s4[i];
        if (tid < 128) {
            sb0[tid] = b0[tid];
            sb1[tid] = b1[tid];
        }
        sbn[tid] = gbn[tid];
        sz[tid] = 0.0f;
    }
    __syncthreads();

    // =====================  GRU encoder (100 sequential steps) =====================
    float* sgA = sk;        // 768: ig(+bias) for all gates
    float* sgH = sk + 768;  // 256: hg for the n-gate only
    for (int s = 0; s < L_; s++) {
        if (tid < 24) {
            float xv;
            if (tid < 8) xv = y_past[(b * L_ + s) * S_ + tid];
            else if (tid < 23) xv = cx[(b * T_ + s) * (XC_ - 1) + (tid - 8)];
            else xv = t[s];
            sx[tid] = xv;
        }
        __syncthreads();
        for (int row = wid; row < 768; row += 8) {
            float vi = (lane < 24) ? wih[row * 24 + lane] * sx[lane] : 0.0f;
            float vh = 0.0f;
            const float* wr = whh + row * 256;
#pragma unroll
            for (int k = 0; k < 8; k++) vh = fmaf(wr[k * 32 + lane], sz[k * 32 + lane], vh);
            if (row < 512) {
                float v = warp_red(vi + vh);
                if (lane == 0) sgA[row] = v + gb[row];
            } else {
                vi = warp_red(vi);
                vh = warp_red(vh);
                if (lane == 0) {
                    sgA[row] = vi + gb[row];
                    sgH[row - 512] = vh;
                }
            }
        }
        __syncthreads();
        {
            int i = tid;
            float r = sigmoid_(sgA[i]);
            float u = sigmoid_(sgA[256 + i]);
            float n = tanhf(fmaf(r, sgH[i] + sbn[i], sgA[512 + i]));
            sz[i] = n + u * (sz[i] - n);
        }
        __syncthreads();
    }

    // readout: warp w computes output channel w (8 warps, 8 channels)
    auto readout = [&](int idx) {
        const float* wr = row_ + wid * 256;
        float v = 0.0f;
#pragma unroll
        for (int k = 0; k < 8; k++) v = fmaf(wr[k * 32 + lane], sz[k * 32 + lane], v);
        v = warp_red(v);
        if (lane == 0) out[(b * L_ + idx) * O_ + wid] = v + rob[wid];
    };

    readout(0);

    // zero the k buffers (they aliased GRU scratch)
    for (int i = tid; i < 1536; i += 256) sk[i] = 0.0f;
    __syncthreads();

    // =====================  CDE: 99 intervals x 2 dopri5 substeps =====================
    for (int iv = 0; iv < T_ - L_ - 1; iv++) {
        if (tid < 16) {
            int s = L_ + iv;
            float dtv = t[s + 1] - t[s];
            float x0 = (tid < 15) ? cx[(b * T_ + s) * 15 + tid] : t[s];
            float x1 = (tid < 15) ? cx[(b * T_ + s + 1) * 15 + tid] : t[s + 1];
            sdx[tid] = (x1 - x0) / dtv;
            if (tid == 0) smisc[0] = dtv;
        }
        __syncthreads();
        const float hs = smisc[0] * 0.5f;

        for (int sub = 0; sub < 2; sub++) {
            float* k0 = sk;
            float* k1 = sk + 256;
            float* k2 = sk + 512;
            float* k3 = sk + 768;
            float* k4 = sk + 1024;
            float* k5 = sk + 1280;

            // stage 0
            szt[tid] = sz[tid];
            __syncthreads();
            vf_eval(sW0, sW1, sB2, sb0, sb1, szt, sdx, W2v, sa0, sa1, k0, wid, lane);
            // stage 1
            szt[tid] = fmaf(hs * 0.2f, k0[tid], sz[tid]);
            __syncthreads();
            vf_eval(sW0, sW1, sB2, sb0, sb1, szt, sdx, W2v, sa0, sa1, k1, wid, lane);
            // stage 2
            {
                float v = 0.075f * k0[tid] + 0.225f * k1[tid];
                szt[tid] = fmaf(hs, v, sz[tid]);
            }
            __syncthreads();
            vf_eval(sW0, sW1, sB2, sb0, sb1, szt, sdx, W2v, sa0, sa1, k2, wid, lane);
            // stage 3
            {
                float v = (44.0f / 45.0f) * k0[tid] + (-56.0f / 15.0f) * k1[tid] +
                          (32.0f / 9.0f) * k2[tid];
                szt[tid] = fmaf(hs, v, sz[tid]);
            }
            __syncthreads();
            vf_eval(sW0, sW1, sB2, sb0, sb1, szt, sdx, W2v, sa0, sa1, k3, wid, lane);
            // stage 4
            {
                float v = (19372.0f / 6561.0f) * k0[tid] + (-25360.0f / 2187.0f) * k1[tid] +
                          (64448.0f / 6561.0f) * k2[tid] + (-212.0f / 729.0f) * k3[tid];
                szt[tid] = fmaf(hs, v, sz[tid]);
            }
            __syncthreads();
            vf_eval(sW0, sW1, sB2, sb0, sb1, szt, sdx, W2v, sa0, sa1, k4, wid, lane);
            // stage 5
            {
                float v = (9017.0f / 3168.0f) * k0[tid] + (-355.0f / 33.0f) * k1[tid] +
                          (46732.0f / 5247.0f) * k2[tid] + (49.0f / 176.0f) * k3[tid] +
                          (-5103.0f / 18656.0f) * k4[tid];
                szt[tid] = fmaf(hs, v, sz[tid]);
            }
            __syncthreads();
            vf_eval(sW0, sW1, sB2, sb0, sb1, szt, sdx, W2v, sa0, sa1, k5, wid, lane);
            // combine
            {
                float v = (35.0f / 384.0f) * k0[tid] + (500.0f / 1113.0f) * k2[tid] +
                          (125.0f / 192.0f) * k3[tid] + (-2187.0f / 6784.0f) * k4[tid] +
                          (11.0f / 84.0f) * k5[tid];
                sz[tid] = fmaf(hs, v, sz[tid]);
            }
            __syncthreads();
        }
        readout(iv + 1);
        __syncthreads();
    }
}

extern "C" void kernel_launch(void* const* d_in, const int* in_sizes, int n_in,
                              void* d_out, int out_size) {
    (void)in_sizes;
    (void)n_in;
    (void)out_size;
    const size_t smem_bytes = SMEM_FLOATS * sizeof(float);
    cudaFuncSetAttribute(grucde_kernel, cudaFuncAttributeMaxDynamicSharedMemorySize,
                         (int)smem_bytes);
    grucde_kernel<<<B_, 256, smem_bytes>>>(
        (const float*)d_in[0], (const float*)d_in[1], (const float*)d_in[2],
        (const float*)d_in[3], (const float*)d_in[4], (const float*)d_in[5],
        (const float*)d_in[6], (const float*)d_in[7], (const float*)d_in[8],
        (const float*)d_in[9], (const float*)d_in[10], (const float*)d_in[11],
        (const float*)d_in[12], (const float*)d_in[13], (const float*)d_in[14],
        (float*)d_out);
}

// round 7
// speedup vs baseline: 1.0295x; 1.0295x over previous
#include <cuda_runtime.h>
#include <math.h>

#define B_ 64
#define T_ 200
#define L_ 100
#define S_ 8
#define XC_ 16
#define H_ 256
#define W_ 128
#define O_ 8

#define NTHREADS 512

// ---------------- smem layout (floats) ----------------
#define OFF_W0 0            // 32768  (mlp_w0 128x256)
#define OFF_W1 32768        // 16384  (mlp_w1 128x128)
#define OFF_B2 49152        // 4096
#define OFF_b0 53248        // 128
#define OFF_b1 53376        // 128
#define OFF_bn 53504        // 256
#define OFF_z  53760        // 512   (2 batches x 256)
#define OFF_zt 54272        // 512
#define OFF_a0 54784        // 256   (2 x 128)
#define OFF_a1 55040        // 256
#define OFF_k  55296        // 2560  (k-buffers; also GRU gate scratch 2x1024)
#define OFF_dx 57856        // 32    (2 x 16)
#define OFF_x  57888        // 64    (2 x 24, padded)
#define OFF_ms 57952        // 8
#define SMEM_FLOATS 57960   // 231840 bytes

// ---------------- round-2 FROZEN math (bit-exact) ----------------
__device__ __forceinline__ float warp_red(float v) {
    v += __shfl_xor_sync(0xffffffffu, v, 16);
    v += __shfl_xor_sync(0xffffffffu, v, 8);
    v += __shfl_xor_sync(0xffffffffu, v, 4);
    v += __shfl_xor_sync(0xffffffffu, v, 2);
    v += __shfl_xor_sync(0xffffffffu, v, 1);
    return v;
}

__device__ __forceinline__ float softplus_(float x) {
    float e = __expf(-fabsf(x));
    return fmaxf(x, 0.0f) + __logf(1.0f + e);
}

__device__ __forceinline__ float sigmoid_(float x) {
    return 1.0f / (1.0f + __expf(-x));
}

// ---------------- vf for 2 batches (per-batch arithmetic == round 2) ----------------
// Warps 0-7: batch 0 rows for stages 1/2; warps 8-15: batch 1.
// Stage 3: all 16 warps cover h=0..255; each W2 load feeds BOTH batches.
__device__ void vf_eval(float* sm, const float4* __restrict__ W2v,
                        float* __restrict__ kout, int wid, int lane) {
    const int g = lane >> 3;
    const int l8 = lane & 7;
    const int m = wid >> 3;       // batch this warp serves in stages 1/2
    const int w8 = wid & 7;

    const float* sW0 = sm + OFF_W0;
    const float* sW1 = sm + OFF_W1;
    const float* sB2 = sm + OFF_B2;
    const float* sb0 = sm + OFF_b0;
    const float* sb1 = sm + OFF_b1;
    float* sa0 = sm + OFF_a0;
    float* sa1 = sm + OFF_a1;
    const float* szt = sm + OFF_zt;
    const float* sdx = sm + OFF_dx;

    // ---- stage 1: a0 = softplus(W0 @ zt + b0) ---- (round-2 inner loop verbatim)
    {
        const float* zin = szt + m * 256;
        for (int row = w8; row < W_; row += 8) {
            const float* wr = sW0 + row * H_;
            float v = 0.0f;
#pragma unroll
            for (int k = 0; k < 8; k++) v = fmaf(wr[k * 32 + lane], zin[k * 32 + lane], v);
            v = warp_red(v);
            if (lane == 0) sa0[m * 128 + row] = softplus_(v + sb0[row]);
        }
    }
    __syncthreads();

    // ---- stage 2: a1 = softplus(W1 @ a0 + b1) ----
    {
        const float* a0in = sa0 + m * 128;
        for (int row = w8; row < W_; row += 8) {
            const float* wr = sW1 + row * W_;
            float v = 0.0f;
#pragma unroll
            for (int k = 0; k < 4; k++) v = fmaf(wr[k * 32 + lane], a0in[k * 32 + lane], v);
            v = warp_red(v);
            if (lane == 0) sa1[m * 128 + row] = softplus_(v + sb1[row]);
        }
    }
    __syncthreads();

    // ---- stage 3: W2 (4096x128) matvec for BOTH batches + tanh + dx contraction ----
    // 16 warps x 16 h each. Per (h,it): group g owns row h*16+it*4+g, lane l8
    // loads 4 float4 slots (round-2 pattern). One tanhf issue covers both
    // batches via the l8<4 lane split (pure lane re-assignment, no numeric change).
    float4 ra0[4], ra1[4];
    const float4* a1v = (const float4*)sa1;
#pragma unroll
    for (int j = 0; j < 4; j++) {
        ra0[j] = a1v[j * 8 + l8];
        ra1[j] = a1v[32 + j * 8 + l8];
    }
    float dxsel[4];
#pragma unroll
    for (int it = 0; it < 4; it++)
        dxsel[it] = (l8 < 4) ? sdx[it * 4 + g] : sdx[16 + it * 4 + g];

    const int hbase = wid * 16;
#pragma unroll 2
    for (int i = 0; i < 16; i++) {
        const int h = hbase + i;
        float ks = 0.0f;
#pragma unroll
        for (int it = 0; it < 4; it++) {
            int row = (h << 4) + (it << 2) + g;
            const float4* wp = W2v + (size_t)row * 32 + l8;
            float4 w0 = __ldg(wp);
            float4 w1 = __ldg(wp + 8);
            float4 w2 = __ldg(wp + 16);
            float4 w3 = __ldg(wp + 24);
            // batch-0 chain: verbatim round-2 order
            float s0 = w0.x * ra0[0].x;
            s0 = fmaf(w0.y, ra0[0].y, s0);
            s0 = fmaf(w0.z, ra0[0].z, s0);
            s0 = fmaf(w0.w, ra0[0].w, s0);
            s0 = fmaf(w1.x, ra0[1].x, s0);
            s0 = fmaf(w1.y, ra0[1].y, s0);
            s0 = fmaf(w1.z, ra0[1].z, s0);
            s0 = fmaf(w1.w, ra0[1].w, s0);
            s0 = fmaf(w2.x, ra0[2].x, s0);
            s0 = fmaf(w2.y, ra0[2].y, s0);
            s0 = fmaf(w2.z, ra0[2].z, s0);
            s0 = fmaf(w2.w, ra0[2].w, s0);
            s0 = fmaf(w3.x, ra0[3].x, s0);
            s0 = fmaf(w3.y, ra0[3].y, s0);
            s0 = fmaf(w3.z, ra0[3].z, s0);
            s0 = fmaf(w3.w, ra0[3].w, s0);
            // batch-1 chain: identical order on batch-1 operands
            float s1 = w0.x * ra1[0].x;
            s1 = fmaf(w0.y, ra1[0].y, s1);
            s1 = fmaf(w0.z, ra1[0].z, s1);
            s1 = fmaf(w0.w, ra1[0].w, s1);
            s1 = fmaf(w1.x, ra1[1].x, s1);
            s1 = fmaf(w1.y, ra1[1].y, s1);
            s1 = fmaf(w1.z, ra1[1].z, s1);
            s1 = fmaf(w1.w, ra1[1].w, s1);
            s1 = fmaf(w2.x, ra1[2].x, s1);
            s1 = fmaf(w2.y, ra1[2].y, s1);
            s1 = fmaf(w2.z, ra1[2].z, s1);
            s1 = fmaf(w2.w, ra1[2].w, s1);
            s1 = fmaf(w3.x, ra1[3].x, s1);
            s1 = fmaf(w3.y, ra1[3].y, s1);
            s1 = fmaf(w3.z, ra1[3].z, s1);
            s1 = fmaf(w3.w, ra1[3].w, s1);
            // round-2 group reduce order (xor 1,2,4) per batch
            s0 += __shfl_xor_sync(0xffffffffu, s0, 1);
            s1 += __shfl_xor_sync(0xffffffffu, s1, 1);
            s0 += __shfl_xor_sync(0xffffffffu, s0, 2);
            s1 += __shfl_xor_sync(0xffffffffu, s1, 2);
            s0 += __shfl_xor_sync(0xffffffffu, s0, 4);
            s1 += __shfl_xor_sync(0xffffffffu, s1, 4);
            float bb = sB2[row];
            // lane split: l8<4 -> batch 0, l8>=4 -> batch 1 (one tanhf issue)
            float x = (l8 < 4) ? (s0 + bb) : (s1 + bb);
            float tv = tanhf(x);
            ks = fmaf(tv, dxsel[it], ks);
        }
        // sum over the 4 groups (same xor8/xor16 tree as round 2)
        ks += __shfl_xor_sync(0xffffffffu, ks, 8);
        ks += __shfl_xor_sync(0xffffffffu, ks, 16);
        if (lane == 0) kout[h] = ks;          // l8==0 -> batch 0
        else if (lane == 4) kout[256 + h] = ks;  // l8==4 -> batch 1
    }
    __syncthreads();
}

extern "C" __global__ void __launch_bounds__(NTHREADS, 1)
grucde_kernel(const float* __restrict__ y_past, const float* __restrict__ t,
              const float* __restrict__ cx, const float* __restrict__ wih,
              const float* __restrict__ whh, const float* __restrict__ gb,
              const float* __restrict__ gbn, const float* __restrict__ w0,
              const float* __restrict__ b0, const float* __restrict__ w1,
              const float* __restrict__ b1, const float* __restrict__ w2,
              const float* __restrict__ b2, const float* __restrict__ row_,
              const float* __restrict__ rob, float* __restrict__ out) {
    extern __shared__ float sm[];
    const int tid = threadIdx.x;
    const int wid = tid >> 5;
    const int lane = tid & 31;
    const int b0i = blockIdx.x * 2;
    const float4* W2v = (const float4*)w2;

    float* sz = sm + OFF_z;
    float* szt = sm + OFF_zt;
    float* sk = sm + OFF_k;
    float* sdx = sm + OFF_dx;
    float* sx = sm + OFF_x;
    float* sbn = sm + OFF_bn;
    float* sms = sm + OFF_ms;

    // ---- stage weights into SMEM ----
    {
        float4* d = (float4*)(sm + OFF_W0);
        const float4* s4 = (const float4*)w0;
        for (int i = tid; i < 8192; i += NTHREADS) d[i] = s4[i];
        d = (float4*)(sm + OFF_W1);
        s4 = (const float4*)w1;
        for (int i = tid; i < 4096; i += NTHREADS) d[i] = s4[i];
        d = (float4*)(sm + OFF_B2);
        s4 = (const float4*)b2;
        for (int i = tid; i < 1024; i += NTHREADS) d[i] = s4[i];
        if (tid < 128) {
            sm[OFF_b0 + tid] = b0[tid];
            sm[OFF_b1 + tid] = b1[tid];
        }
        if (tid < 256) sbn[tid] = gbn[tid];
        sz[tid] = 0.0f;
    }
    __syncthreads();

    // ============ GRU encoder: 100 sequential steps, 2 batches ============
    // warps 0-7 -> batch 0 (round-2 code verbatim), warps 8-15 -> batch 1.
    // gate scratch: sk[m*1024 + 0..768) = gates, sk[m*1024 + 768..1024) = hn
    {
        const int m = wid >> 3;
        const int w8 = wid & 7;
        float* sgA = sk + m * 1024;
        float* sgH = sk + m * 1024 + 768;
        const float* sxm = sx + m * 24;
        const float* szm = sz + m * 256;
        for (int s = 0; s < L_; s++) {
            if (tid < 48) {
                int mm = tid / 24, j = tid % 24;
                float xv;
                if (j < 8) xv = y_past[((b0i + mm) * L_ + s) * S_ + j];
                else if (j < 23) xv = cx[((b0i + mm) * T_ + s) * (XC_ - 1) + (j - 8)];
                else xv = t[s];
                sx[mm * 24 + j] = xv;
            }
            __syncthreads();
            for (int row = w8; row < 768; row += 8) {
                float vi = (lane < 24) ? wih[row * 24 + lane] * sxm[lane] : 0.0f;
                float vh = 0.0f;
                const float* wr = whh + row * 256;
#pragma unroll
                for (int k = 0; k < 8; k++) vh = fmaf(wr[k * 32 + lane], szm[k * 32 + lane], vh);
                if (row < 512) {
                    float v = warp_red(vi + vh);
                    if (lane == 0) sgA[row] = v + gb[row];
                } else {
                    vi = warp_red(vi);
                    vh = warp_red(vh);
                    if (lane == 0) {
                        sgA[row] = vi + gb[row];
                        sgH[row - 512] = vh;
                    }
                }
            }
            __syncthreads();
            {
                int mm = tid >> 8, i = tid & 255;
                float* gm = sk + mm * 1024;
                float r = sigmoid_(gm[i]);
                float u = sigmoid_(gm[256 + i]);
                float n = tanhf(fmaf(r, gm[768 + i] + sbn[i], gm[512 + i]));
                float zv = sz[mm * 256 + i];
                sz[mm * 256 + i] = n + u * (zv - n);
            }
            __syncthreads();
        }
    }

    // readout: warp w -> batch (w>>3), channel (w&7); round-2 arithmetic
    auto readout = [&](int idx) {
        int m = wid >> 3, ch = wid & 7;
        const float* wr = row_ + ch * 256;
        const float* zm = sz + m * 256;
        float v = 0.0f;
#pragma unroll
        for (int k = 0; k < 8; k++) v = fmaf(wr[k * 32 + lane], zm[k * 32 + lane], v);
        v = warp_red(v);
        if (lane == 0) out[((b0i + m) * L_ + idx) * O_ + ch] = v + rob[ch];
    };

    readout(0);

    // zero the k buffers (they aliased GRU scratch)
    for (int i = tid; i < 2560; i += NTHREADS) sk[i] = 0.0f;
    __syncthreads();

    // k-buffers (512 floats each); k5 reuses k1's slot (k1 dead by then)
    float* kb0 = sk;
    float* kb1 = sk + 512;
    float* kb2 = sk + 1024;
    float* kb3 = sk + 1536;
    float* kb4 = sk + 2048;
    float* kb5 = sk + 512;

    const int si = tid;  // element (m = tid>>8, i = tid&255)

    // ============ CDE: 99 intervals x 2 dopri5 substeps ============
    for (int iv = 0; iv < T_ - L_ - 1; iv++) {
        if (tid < 32) {
            int m = tid >> 4, j = tid & 15;
            int s = L_ + iv;
            float dtv = t[s + 1] - t[s];
            float x0v = (j < 15) ? cx[((b0i + m) * T_ + s) * 15 + j] : t[s];
            float x1v = (j < 15) ? cx[((b0i + m) * T_ + s + 1) * 15 + j] : t[s + 1];
            sdx[m * 16 + j] = (x1v - x0v) / dtv;
            if (tid == 0) sms[0] = dtv;
        }
        __syncthreads();
        const float hs = sms[0] * 0.5f;

        for (int sub = 0; sub < 2; sub++) {
            // stage 0
            szt[si] = sz[si];
            __syncthreads();
            vf_eval(sm, W2v, kb0, wid, lane);
            // stage 1
            szt[si] = fmaf(hs * 0.2f, kb0[si], sz[si]);
            __syncthreads();
            vf_eval(sm, W2v, kb1, wid, lane);
            // stage 2
            {
                float v = 0.075f * kb0[si] + 0.225f * kb1[si];
                szt[si] = fmaf(hs, v, sz[si]);
            }
            __syncthreads();
            vf_eval(sm, W2v, kb2, wid, lane);
            // stage 3
            {
                float v = (44.0f / 45.0f) * kb0[si] + (-56.0f / 15.0f) * kb1[si] +
                          (32.0f / 9.0f) * kb2[si];
                szt[si] = fmaf(hs, v, sz[si]);
            }
            __syncthreads();
            vf_eval(sm, W2v, kb3, wid, lane);
            // stage 4
            {
                float v = (19372.0f / 6561.0f) * kb0[si] + (-25360.0f / 2187.0f) * kb1[si] +
                          (64448.0f / 6561.0f) * kb2[si] + (-212.0f / 729.0f) * kb3[si];
                szt[si] = fmaf(hs, v, sz[si]);
            }
            __syncthreads();
            vf_eval(sm, W2v, kb4, wid, lane);
            // stage 5 (k1 consumed here for the last time; k5 overwrites its slot)
            {
                float v = (9017.0f / 3168.0f) * kb0[si] + (-355.0f / 33.0f) * kb1[si] +
                          (46732.0f / 5247.0f) * kb2[si] + (49.0f / 176.0f) * kb3[si] +
                          (-5103.0f / 18656.0f) * kb4[si];
                szt[si] = fmaf(hs, v, sz[si]);
            }
            __syncthreads();
            vf_eval(sm, W2v, kb5, wid, lane);
            // combine
            {
                float v = (35.0f / 384.0f) * kb0[si] + (500.0f / 1113.0f) * kb2[si] +
                          (125.0f / 192.0f) * kb3[si] + (-2187.0f / 6784.0f) * kb4[si] +
                          (11.0f / 84.0f) * kb5[si];
                sz[si] = fmaf(hs, v, sz[si]);
            }
            __syncthreads();
        }
        readout(iv + 1);
        __syncthreads();
    }
}

extern "C" void kernel_launch(void* const* d_in, const int* in_sizes, int n_in,
                              void* d_out, int out_size) {
    (void)in_sizes;
    (void)n_in;
    (void)out_size;
    const size_t smem_bytes = SMEM_FLOATS * sizeof(float);
    cudaFuncSetAttribute(grucde_kernel, cudaFuncAttributeMaxDynamicSharedMemorySize,
                         (int)smem_bytes);
    grucde_kernel<<<B_ / 2, NTHREADS, smem_bytes>>>(
        (const float*)d_in[0], (const float*)d_in[1], (const float*)d_in[2],
        (const float*)d_in[3], (const float*)d_in[4], (const float*)d_in[5],
        (const float*)d_in[6], (const float*)d_in[7], (const float*)d_in[8],
        (const float*)d_in[9], (const float*)d_in[10], (const float*)d_in[11],
        (const float*)d_in[12], (const float*)d_in[13], (const float*)d_in[14],
        (float*)d_out);
}

// round 9
// speedup vs baseline: 1.0950x; 1.0637x over previous
#include <cuda_runtime.h>
#include <math.h>

#define B_ 64
#define T_ 200
#define L_ 100
#define S_ 8
#define XC_ 16
#define H_ 256
#define W_ 128
#define O_ 8

#define NTHREADS 512

typedef unsigned long long u64;

// 2MB packed W2: for h in 0..255, pp in 0..7, k in 0..127:
//   c_lo = (pp&3) + 8*(pp>>2), c_hi = c_lo + 4
//   W2P[((h*8+pp)*128 + k)*2 + 0] = w2[(h*16+c_lo)*128 + k]
//   W2P[((h*8+pp)*128 + k)*2 + 1] = w2[(h*16+c_hi)*128 + k]
#define W2P_ELEMS (2 * 128 * 8 * 256)   // 524288 floats
__device__ float g_W2P[W2P_ELEMS];

// ---------------- smem layout (floats) ----------------
#define OFF_W0 0            // 32768  (mlp_w0 128x256)
#define OFF_W1 32768        // 16384  (mlp_w1 128x128)
#define OFF_B2 49152        // 4096
#define OFF_b0 53248        // 128
#define OFF_b1 53376        // 128
#define OFF_bn 53504        // 256
#define OFF_z  53760        // 256
#define OFF_zt 54016        // 256
#define OFF_a0 54272        // 128
#define OFF_a1 54400        // 128
#define OFF_k  54528        // 1536  (k-buffers; aliases GRU gate scratch 1024)
#define OFF_dx 56064        // 16
#define OFF_x  56080        // 32
#define OFF_ms 56112        // 8
#define SMEM_FLOATS 56120   // 224480 bytes

// ---------------- round-2 FROZEN math (bit-exact) ----------------
__device__ __forceinline__ float warp_red(float v) {
    v += __shfl_xor_sync(0xffffffffu, v, 16);
    v += __shfl_xor_sync(0xffffffffu, v, 8);
    v += __shfl_xor_sync(0xffffffffu, v, 4);
    v += __shfl_xor_sync(0xffffffffu, v, 2);
    v += __shfl_xor_sync(0xffffffffu, v, 1);
    return v;
}

__device__ __forceinline__ float softplus_(float x) {
    float e = __expf(-fabsf(x));
    return fmaxf(x, 0.0f) + __logf(1.0f + e);
}

__device__ __forceinline__ float sigmoid_(float x) {
    return 1.0f / (1.0f + __expf(-x));
}

// ---------------- packed f32x2 helpers (per-component == scalar fma.rn/add.rn) ----
__device__ __forceinline__ u64 ffma2(u64 a, u64 b, u64 c) {
    u64 d;
    asm("fma.rn.f32x2 %0, %1, %2, %3;" : "=l"(d) : "l"(a), "l"(b), "l"(c));
    return d;
}

__device__ __forceinline__ u64 add2(u64 a, u64 b) {
    u64 d;
    asm("add.rn.f32x2 %0, %1, %2;" : "=l"(d) : "l"(a), "l"(b));
    return d;
}

__device__ __forceinline__ u64 dup2(float v) {
    u64 d;
    asm("mov.b64 %0, {%1, %1};" : "=l"(d) : "f"(v));
    return d;
}

__device__ __forceinline__ float2 unpack2(u64 a) {
    float2 r;
    asm("mov.b64 {%0,%1}, %2;" : "=f"(r.x), "=f"(r.y) : "l"(a));
    return r;
}

__device__ __forceinline__ u64 shfl64(u64 v, int m) {
    unsigned lo = (unsigned)v, hi = (unsigned)(v >> 32);
    lo = __shfl_xor_sync(0xffffffffu, lo, m);
    hi = __shfl_xor_sync(0xffffffffu, hi, m);
    return ((u64)hi << 32) | lo;
}

// ---------------- vf: 1 batch, 16 warps ----------------
// a0 = softplus(W0 @ zt + b0); a1 = softplus(W1 @ a0 + b1);
// f = tanh(W2 @ a1 + b2); k[h] = sum_c f[h*16+c]*dx[c]
// Per-row arithmetic verbatim round 2; stage 3 uses row-pair f32x2 packing
// (each component's op sequence identical to the round-2 scalar chain).
__device__ void vf_eval(float* sm, float* __restrict__ kout, int wid, int lane) {
    const int g = lane >> 3;
    const int l8 = lane & 7;

    const float* sW0 = sm + OFF_W0;
    const float* sW1 = sm + OFF_W1;
    const float* sB2 = sm + OFF_B2;
    const float* sb0 = sm + OFF_b0;
    const float* sb1 = sm + OFF_b1;
    float* sa0 = sm + OFF_a0;
    float* sa1 = sm + OFF_a1;
    const float* szt = sm + OFF_zt;
    const float* sdx = sm + OFF_dx;

    // ---- stage 1: a0 (128 rows x 256), rows stride 16 over warps ----
    for (int row = wid; row < W_; row += 16) {
        const float* wr = sW0 + row * H_;
        float v = 0.0f;
#pragma unroll
        for (int k = 0; k < 8; k++) v = fmaf(wr[k * 32 + lane], szt[k * 32 + lane], v);
        v = warp_red(v);
        if (lane == 0) sa0[row] = softplus_(v + sb0[row]);
    }
    __syncthreads();

    // ---- stage 2: a1 (128 rows x 128) ----
    for (int row = wid; row < W_; row += 16) {
        const float* wr = sW1 + row * W_;
        float v = 0.0f;
#pragma unroll
        for (int k = 0; k < 4; k++) v = fmaf(wr[k * 32 + lane], sa0[k * 32 + lane], v);
        v = warp_red(v);
        if (lane == 0) sa1[row] = softplus_(v + sb1[row]);
    }
    __syncthreads();

    // ---- stage 3: row-pair packed W2 matvec + tanh + dx contraction ----
    // Group g, pair-iter q: rows (c_lo = g+8q, c_hi = g+8q+4) of h's 16-block.
    // Lane l8 owns k = {4l8..+3, 32+4l8..+3, 64+.., 96+..} (round-2 order).
    u64 a1d[16];
    {
        const float4* a1v = (const float4*)sa1;
#pragma unroll
        for (int jj = 0; jj < 4; jj++) {
            float4 t = a1v[jj * 8 + l8];
            a1d[4 * jj + 0] = dup2(t.x);
            a1d[4 * jj + 1] = dup2(t.y);
            a1d[4 * jj + 2] = dup2(t.z);
            a1d[4 * jj + 3] = dup2(t.w);
        }
    }
    float dxsel[4];
#pragma unroll
    for (int it = 0; it < 4; it++) dxsel[it] = sdx[it * 4 + g];
    const int odd = l8 & 1;

    const int hbase = wid * 16;
#pragma unroll 2
    for (int i = 0; i < 16; i++) {
        const int h = hbase + i;
        float ks = 0.0f;
#pragma unroll
        for (int q = 0; q < 2; q++) {
            const float* wp = g_W2P + ((h * 8 + g + 4 * q) << 8) + 8 * l8;
            u64 acc = 0ULL;  // {s_lo, s_hi}; fma(w,a,0) == rn(w*a) == round-2 leading MUL
#pragma unroll
            for (int jj = 0; jj < 4; jj++) {
                float4 wa = __ldg((const float4*)(wp + 64 * jj));
                float4 wb = __ldg((const float4*)(wp + 64 * jj + 4));
                const u64* ua = (const u64*)&wa;
                const u64* ub = (const u64*)&wb;
                acc = ffma2(ua[0], a1d[4 * jj + 0], acc);
                acc = ffma2(ua[1], a1d[4 * jj + 1], acc);
                acc = ffma2(ub[0], a1d[4 * jj + 2], acc);
                acc = ffma2(ub[1], a1d[4 * jj + 3], acc);
            }
            // packed xor 1,2,4 reduce (component-wise == round-2 scalar tree)
            acc = add2(acc, shfl64(acc, 1));
            acc = add2(acc, shfl64(acc, 2));
            acc = add2(acc, shfl64(acc, 4));
            // one tanhf issue covers the pair: even lanes -> c_lo, odd -> c_hi
            float2 sv = unpack2(acc);
            int c = g + 8 * q + 4 * odd;
            float bb = sB2[h * 16 + c];
            float x = (odd ? sv.y : sv.x) + bb;
            float tv = tanhf(x);
            float tw = __shfl_xor_sync(0xffffffffu, tv, 1);
            float tvA = odd ? tw : tv;  // tanh for c_lo  (it = 2q)
            float tvB = odd ? tv : tw;  // tanh for c_hi  (it = 2q+1)
            ks = fmaf(tvA, dxsel[2 * q], ks);
            ks = fmaf(tvB, dxsel[2 * q + 1], ks);
        }
        // cross-group tree (round-2 xor8/xor16 order)
        ks += __shfl_xor_sync(0xffffffffu, ks, 8);
        ks += __shfl_xor_sync(0xffffffffu, ks, 16);
        if (lane == 0) kout[h] = ks;
    }
    __syncthreads();
}

// ---------------- W2 pack kernel ----------------
// EXACTLY W2P_ELEMS threads: 1024 blocks x 512 threads = 524288.
extern "C" __global__ void pack_w2_kernel(const float* __restrict__ w2) {
    int idx = blockIdx.x * blockDim.x + threadIdx.x;  // 0 .. W2P_ELEMS-1
    int half = idx & 1;
    int k = (idx >> 1) & 127;
    int pp = (idx >> 8) & 7;
    int h = idx >> 11;  // 0..255
    int c = (pp & 3) + 8 * (pp >> 2) + 4 * half;
    g_W2P[idx] = w2[(h * 16 + c) * 128 + k];
}

extern "C" __global__ void __launch_bounds__(NTHREADS, 1)
grucde_kernel(const float* __restrict__ y_past, const float* __restrict__ t,
              const float* __restrict__ cx, const float* __restrict__ wih,
              const float* __restrict__ whh, const float* __restrict__ gb,
              const float* __restrict__ gbn, const float* __restrict__ w0,
              const float* __restrict__ b0, const float* __restrict__ w1,
              const float* __restrict__ b1, const float* __restrict__ w2,
              const float* __restrict__ b2, const float* __restrict__ row_,
              const float* __restrict__ rob, float* __restrict__ out) {
    extern __shared__ float sm[];
    const int tid = threadIdx.x;
    const int wid = tid >> 5;
    const int lane = tid & 31;
    const int b = blockIdx.x;

    float* sz = sm + OFF_z;
    float* szt = sm + OFF_zt;
    float* sk = sm + OFF_k;
    float* sdx = sm + OFF_dx;
    float* sx = sm + OFF_x;
    float* sbn = sm + OFF_bn;
    float* sms = sm + OFF_ms;

    // ---- stage weights into SMEM ----
    {
        float4* d = (float4*)(sm + OFF_W0);
        const float4* s4 = (const float4*)w0;
        for (int i = tid; i < 8192; i += NTHREADS) d[i] = s4[i];
        d = (float4*)(sm + OFF_W1);
        s4 = (const float4*)w1;
        for (int i = tid; i < 4096; i += NTHREADS) d[i] = s4[i];
        d = (float4*)(sm + OFF_B2);
        s4 = (const float4*)b2;
        for (int i = tid; i < 1024; i += NTHREADS) d[i] = s4[i];
        if (tid < 128) {
            sm[OFF_b0 + tid] = b0[tid];
            sm[OFF_b1 + tid] = b1[tid];
        }
        if (tid < 256) {
            sbn[tid] = gbn[tid];
            sz[tid] = 0.0f;
        }
    }
    __syncthreads();

    // ============ GRU encoder: 100 sequential steps (round-2 per-row code) ============
    // gate scratch: sk[0..768) = gates, sk[768..1024) = hn
    {
        float* sgA = sk;
        float* sgH = sk + 768;
        for (int s = 0; s < L_; s++) {
            if (tid < 24) {
                float xv;
                if (tid < 8) xv = y_past[(b * L_ + s) * S_ + tid];
                else if (tid < 23) xv = cx[(b * T_ + s) * (XC_ - 1) + (tid - 8)];
                else xv = t[s];
                sx[tid] = xv;
            }
            __syncthreads();
            for (int row = wid; row < 768; row += 16) {
                float vi = (lane < 24) ? wih[row * 24 + lane] * sx[lane] : 0.0f;
                float vh = 0.0f;
                const float* wr = whh + row * 256;
#pragma unroll
                for (int k = 0; k < 8; k++) vh = fmaf(wr[k * 32 + lane], sz[k * 32 + lane], vh);
                if (row < 512) {
                    float v = warp_red(vi + vh);
                    if (lane == 0) sgA[row] = v + gb[row];
                } else {
                    vi = warp_red(vi);
                    vh = warp_red(vh);
                    if (lane == 0) {
                        sgA[row] = vi + gb[row];
                        sgH[row - 512] = vh;
                    }
                }
            }
            __syncthreads();
            if (tid < 256) {
                int i = tid;
                float r = sigmoid_(sgA[i]);
                float u = sigmoid_(sgA[256 + i]);
                float n = tanhf(fmaf(r, sgH[i] + sbn[i], sgA[512 + i]));
                sz[i] = n + u * (sz[i] - n);
            }
            __syncthreads();
        }
    }

    // readout: warps 0-7 -> channel wid (round-2 arithmetic)
    auto readout = [&](int idx) {
        if (wid < 8) {
            const float* wr = row_ + wid * 256;
            float v = 0.0f;
#pragma unroll
            for (int k = 0; k < 8; k++) v = fmaf(wr[k * 32 + lane], sz[k * 32 + lane], v);
            v = warp_red(v);
            if (lane == 0) out[(b * L_ + idx) * O_ + wid] = v + rob[wid];
        }
    };

    readout(0);

    // zero the k buffers (they aliased GRU scratch)
    for (int i = tid; i < 1536; i += NTHREADS) sk[i] = 0.0f;
    __syncthreads();

    // k-buffers (256 floats each); k5 reuses k1's slot (k1 dead by then)
    float* kb0 = sk;
    float* kb1 = sk + 256;
    float* kb2 = sk + 512;
    float* kb3 = sk + 768;
    float* kb4 = sk + 1024;
    float* kb5 = sk + 256;

    // ============ CDE: 99 intervals x 2 dopri5 substeps ============
    for (int iv = 0; iv < T_ - L_ - 1; iv++) {
        if (tid < 16) {
            int s = L_ + iv;
            float dtv = t[s + 1] - t[s];
            float x0v = (tid < 15) ? cx[(b * T_ + s) * 15 + tid] : t[s];
            float x1v = (tid < 15) ? cx[(b * T_ + s + 1) * 15 + tid] : t[s + 1];
            sdx[tid] = (x1v - x0v) / dtv;
            if (tid == 0) sms[0] = dtv;
        }
        __syncthreads();
        const float hs = sms[0] * 0.5f;

        for (int sub = 0; sub < 2; sub++) {
            // stage 0
            if (tid < 256) szt[tid] = sz[tid];
            __syncthreads();
            vf_eval(sm, kb0, wid, lane);
            // stage 1
            if (tid < 256) szt[tid] = fmaf(hs * 0.2f, kb0[tid], sz[tid]);
            __syncthreads();
            vf_eval(sm, kb1, wid, lane);
            // stage 2
            if (tid < 256) {
                float v = 0.075f * kb0[tid] + 0.225f * kb1[tid];
                szt[tid] = fmaf(hs, v, sz[tid]);
            }
            __syncthreads();
            vf_eval(sm, kb2, wid, lane);
            // stage 3
            if (tid < 256) {
                float v = (44.0f / 45.0f) * kb0[tid] + (-56.0f / 15.0f) * kb1[tid] +
                          (32.0f / 9.0f) * kb2[tid];
                szt[tid] = fmaf(hs, v, sz[tid]);
            }
            __syncthreads();
            vf_eval(sm, kb3, wid, lane);
            // stage 4
            if (tid < 256) {
                float v = (19372.0f / 6561.0f) * kb0[tid] + (-25360.0f / 2187.0f) * kb1[tid] +
                          (64448.0f / 6561.0f) * kb2[tid] + (-212.0f / 729.0f) * kb3[tid];
                szt[tid] = fmaf(hs, v, sz[tid]);
            }
            __syncthreads();
            vf_eval(sm, kb4, wid, lane);
            // stage 5 (k1 consumed for the last time; k5 overwrites its slot)
            if (tid < 256) {
                float v = (9017.0f / 3168.0f) * kb0[tid] + (-355.0f / 33.0f) * kb1[tid] +
                          (46732.0f / 5247.0f) * kb2[tid] + (49.0f / 176.0f) * kb3[tid] +
                          (-5103.0f / 18656.0f) * kb4[tid];
                szt[tid] = fmaf(hs, v, sz[tid]);
            }
            __syncthreads();
            vf_eval(sm, kb5, wid, lane);
            // combine
            if (tid < 256) {
                float v = (35.0f / 384.0f) * kb0[tid] + (500.0f / 1113.0f) * kb2[tid] +
                          (125.0f / 192.0f) * kb3[tid] + (-2187.0f / 6784.0f) * kb4[tid] +
                          (11.0f / 84.0f) * kb5[tid];
                sz[tid] = fmaf(hs, v, sz[tid]);
            }
            __syncthreads();
        }
        readout(iv + 1);
        __syncthreads();
    }
}

extern "C" void kernel_launch(void* const* d_in, const int* in_sizes, int n_in,
                              void* d_out, int out_size) {
    (void)in_sizes;
    (void)n_in;
    (void)out_size;
    const float* w2 = (const float*)d_in[11];
    pack_w2_kernel<<<W2P_ELEMS / 512, 512>>>(w2);  // 1024 blocks x 512 = exactly W2P_ELEMS
    const size_t smem_bytes = SMEM_FLOATS * sizeof(float);
    cudaFuncSetAttribute(grucde_kernel, cudaFuncAttributeMaxDynamicSharedMemorySize,
                         (int)smem_bytes);
    grucde_kernel<<<B_, NTHREADS, smem_bytes>>>(
        (const float*)d_in[0], (const float*)d_in[1], (const float*)d_in[2],
        (const float*)d_in[3], (const float*)d_in[4], (const float*)d_in[5],
        (const float*)d_in[6], (const float*)d_in[7], (const float*)d_in[8],
        (const float*)d_in[9], (const float*)d_in[10], (const float*)d_in[11],
        (const float*)d_in[12], (const float*)d_in[13], (const float*)d_in[14],
        (float*)d_out);
}